// round 12
// baseline (speedup 1.0000x reference)
#include <cuda_runtime.h>
#include <cuda_bf16.h>
#include <cstdint>

#define NB 1024
#define ND 128
#define TT 64               // square tile
#define NBLK 16             // NB / TT
#define NCTA 256
#define ROWB 768            // 384 bf16 (= [hi|lo|hi] / [hi|hi|lo]) per row

__device__ float g_part[NBLK * NB];   // [j_block][i] partial row sums of exp(sim)
__device__ float g_pos[NB];           // diagonal sims
__device__ unsigned int g_ctr = 0;    // last-CTA ticket (reset each replay)

// ---- smem layout (bytes) ----
#define OFF_RP   0                    // rowpart[2][64] = 512 B
#define OFF_N1   512                  // 64 f
#define OFF_RN1  768
#define OFF_N2   1024
#define OFF_RN2  1280
#define OFF_RED  1536                 // 8 f
#define OFF_FLAG 1568
#define OFF_A    2048                 // 64 x 768 = 49152 B
#define OFF_B    (2048 + 49152)
#define SMEM_TOTAL (OFF_B + 49152)    // 100352 B -> 2 CTAs/SM

__device__ __forceinline__ uint32_t smem_u32(const void* p) {
  uint32_t a;
  asm("{ .reg .u64 t; cvta.to.shared.u64 t, %1; cvt.u32.u64 %0, t; }" : "=r"(a) : "l"(p));
  return a;
}
#define LDSM_X4(r0, r1, r2, r3, addr) \
  asm volatile("ldmatrix.sync.aligned.m8n8.x4.shared.b16 {%0,%1,%2,%3}, [%4];" \
               : "=r"(r0), "=r"(r1), "=r"(r2), "=r"(r3) : "r"(addr))
__device__ __forceinline__ void mma16816(float* d, const uint32_t* a, const uint32_t* b) {
  asm volatile(
      "mma.sync.aligned.m16n8k16.row.col.f32.bf16.bf16.f32 "
      "{%0,%1,%2,%3}, {%4,%5,%6,%7}, {%8,%9}, {%0,%1,%2,%3};"
      : "+f"(d[0]), "+f"(d[1]), "+f"(d[2]), "+f"(d[3])
      : "r"(a[0]), "r"(a[1]), "r"(a[2]), "r"(a[3]), "r"(b[0]), "r"(b[1]));
}
__device__ __forceinline__ uint32_t pack_bf2(__nv_bfloat16 a, __nv_bfloat16 b) {
  return ((uint32_t)__bfloat16_as_ushort(b) << 16) | (uint32_t)__bfloat16_as_ushort(a);
}

// Stage one 64x128 fp32 tile -> compensated-bf16 [seg0|seg1|seg2] in smem,
// XOR-swizzled 16B chunks; also produce per-row sumsq + rsqrt norms.
// A packs [hi|lo|hi] (lo_last=false), B packs [hi|hi|lo] (lo_last=true).
__device__ __forceinline__ void stage_tile(const float* __restrict__ src,
                                           char* smtile, float* snorm, float* srnorm,
                                           int tid, bool lo_last) {
  const int r = tid >> 2, q = tid & 3;
  const float* row = src + (size_t)r * ND;
  char* rbase = smtile + r * ROWB;
  const int s = r & 7;
  float ssq = 0.f;
  #pragma unroll
  for (int i = 0; i < 4; ++i) {
    const int c = q + 4 * i;                      // chunk 0..15 (8 floats)
    float4 v0 = *reinterpret_cast<const float4*>(row + 8 * c);
    float4 v1 = *reinterpret_cast<const float4*>(row + 8 * c + 4);
    float f[8] = {v0.x, v0.y, v0.z, v0.w, v1.x, v1.y, v1.z, v1.w};
    uint32_t hp[4], lp[4];
    #pragma unroll
    for (int k = 0; k < 4; ++k) {
      float a = f[2 * k], b = f[2 * k + 1];
      ssq = fmaf(a, a, ssq); ssq = fmaf(b, b, ssq);
      __nv_bfloat16 ha = __float2bfloat16_rn(a), hb = __float2bfloat16_rn(b);
      __nv_bfloat16 la = __float2bfloat16_rn(a - __bfloat162float(ha));
      __nv_bfloat16 lb = __float2bfloat16_rn(b - __bfloat162float(hb));
      hp[k] = pack_bf2(ha, hb);
      lp[k] = pack_bf2(la, lb);
    }
    const int cs = c ^ s;
    uint4 hv = make_uint4(hp[0], hp[1], hp[2], hp[3]);
    uint4 lv = make_uint4(lp[0], lp[1], lp[2], lp[3]);
    *reinterpret_cast<uint4*>(rbase + cs * 16) = hv;                        // seg0: hi
    *reinterpret_cast<uint4*>(rbase + (16 + cs) * 16) = lo_last ? hv : lv;  // seg1
    *reinterpret_cast<uint4*>(rbase + (32 + cs) * 16) = lo_last ? lv : hv;  // seg2
  }
  ssq += __shfl_xor_sync(0xffffffffu, ssq, 1);
  ssq += __shfl_xor_sync(0xffffffffu, ssq, 2);
  if (q == 0) {
    snorm[r] = ssq;
    srnorm[r] = 1.0f / fmaxf(sqrtf(ssq), 1e-12f);
  }
}

__global__ __launch_bounds__(256, 2) void hyp_fused(const float* __restrict__ z1,
                                                    const float* __restrict__ z2,
                                                    float* __restrict__ out) {
  extern __shared__ char sm[];
  const uint32_t smb = smem_u32(sm);
  float* rowpart = reinterpret_cast<float*>(sm + OFF_RP);
  float* sn1 = reinterpret_cast<float*>(sm + OFF_N1);
  float* srn1 = reinterpret_cast<float*>(sm + OFF_RN1);
  float* sn2 = reinterpret_cast<float*>(sm + OFF_N2);
  float* srn2 = reinterpret_cast<float*>(sm + OFF_RN2);
  float* red = reinterpret_cast<float*>(sm + OFF_RED);
  int* flag = reinterpret_cast<int*>(sm + OFF_FLAG);

  const int tid = threadIdx.x;
  const int wid = tid >> 5;
  const int lane = tid & 31;
  const int wi = wid & 3;        // warp i-position (4 x 16 rows)
  const int wj = wid >> 2;       // warp j-position (2 x 32 cols)
  const int jb = blockIdx.x;
  const int ib = blockIdx.y;
  const int i0 = ib * TT;
  const int j0 = jb * TT;

  // ---- fused stage + convert + norms ----
  stage_tile(z1 + (size_t)i0 * ND, sm + OFF_A, sn1, srn1, tid, false);
  stage_tile(z2 + (size_t)j0 * ND, sm + OFF_B, sn2, srn2, tid, true);
  __syncthreads();

  // ---- ldmatrix addressing ----
  const uint32_t sx = lane & 7;
  const int akof = lane >> 4;
  const int bkof = (lane >> 3) & 1;
  const uint32_t aoff = smb + OFF_A + (wi * 16 + (lane & 15)) * ROWB;
  uint32_t boff[2];
  #pragma unroll
  for (int nt = 0; nt < 2; ++nt)
    boff[nt] = smb + OFF_B + (wj * 32 + nt * 16 + (lane & 7) + ((lane >> 4) << 3)) * ROWB;

  float acc[4][4];
  #pragma unroll
  for (int n = 0; n < 4; ++n)
    #pragma unroll
    for (int e = 0; e < 4; ++e) acc[n][e] = 0.f;

  // ---- main loop: 24 k16 steps over packed K=384 ----
  #pragma unroll 6
  for (int ks = 0; ks < 24; ++ks) {
    uint32_t ar[4], br[2][4];
    LDSM_X4(ar[0], ar[1], ar[2], ar[3], aoff + (((ks * 2 + akof) ^ sx) << 4));
    LDSM_X4(br[0][0], br[0][1], br[0][2], br[0][3], boff[0] + (((ks * 2 + bkof) ^ sx) << 4));
    LDSM_X4(br[1][0], br[1][1], br[1][2], br[1][3], boff[1] + (((ks * 2 + bkof) ^ sx) << 4));
    mma16816(acc[0], ar, &br[0][0]);
    mma16816(acc[1], ar, &br[0][2]);
    mma16816(acc[2], ar, &br[1][0]);
    mma16816(acc[3], ar, &br[1][2]);
  }

  // ---- epilogue: hyperbolic + cosine sim, exp, per-row partial sums ----
  const int tg = lane >> 2, tl = lane & 3;
  const float CC = 0.05f, SQC = 0.22360679774997896f, KD = 22.360679774997896f;

  #pragma unroll
  for (int h = 0; h < 2; ++h) {
    const int rowl = wi * 16 + h * 8 + tg;
    const int ig = i0 + rowl;
    const float n1 = sn1[rowl];
    const float rn1 = srn1[rowl];
    float rs = 0.f;
    #pragma unroll
    for (int ni = 0; ni < 4; ++ni) {
      #pragma unroll
      for (int e = 0; e < 2; ++e) {
        const int col = wj * 32 + ni * 8 + tl * 2 + e;
        const float g = acc[ni][h * 2 + e];
        const float n2 = sn2[col];
        const float xy = -g;
        const float Af = fmaf(0.1f, xy, fmaf(CC, n2, 1.0f));
        const float Bf = 1.0f - CC * n1;
        const float den = fmaxf(fmaf(0.1f, xy, fmaf(CC * CC, n1 * n2, 1.0f)), 1e-6f);
        const float num2 = Af * Af * n1 + Bf * Bf * n2 + 2.0f * Af * Bf * xy;
        const float s = SQC * sqrtf(fmaxf(num2, 0.0f));
        float r = __fdividef(den + s, fmaxf(den - s, 1e-6f * den));
        r = fminf(r, 2.0e6f);
        const float sim = fmaf(5.0f * g, rn1 * srn2[col], -KD * __logf(r));
        if (ig == j0 + col) g_pos[ig] = sim;
        else rs += __expf(sim);
      }
    }
    rs += __shfl_xor_sync(0xffffffffu, rs, 1);
    rs += __shfl_xor_sync(0xffffffffu, rs, 2);
    if (tl == 0) rowpart[wj * TT + rowl] = rs;
  }
  __syncthreads();
  if (tid < TT) g_part[jb * NB + i0 + tid] = rowpart[tid] + rowpart[TT + tid];

  // ---- last-CTA fused final reduction (deterministic order) ----
  __threadfence();
  __syncthreads();
  if (tid == 0) {
    unsigned t = atomicAdd(&g_ctr, 1u);
    *flag = (t == NCTA - 1) ? 1 : 0;
  }
  __syncthreads();
  if (*flag) {
    __threadfence();
    float acc2 = 0.f;
    #pragma unroll
    for (int q = 0; q < 4; ++q) {
      const int i = tid + q * 256;
      float ssum = 0.f;
      #pragma unroll
      for (int b = 0; b < NBLK; ++b) ssum += g_part[b * NB + i];
      acc2 += logf(ssum) - g_pos[i];
    }
    #pragma unroll
    for (int off = 16; off; off >>= 1) acc2 += __shfl_down_sync(0xffffffffu, acc2, off);
    if (lane == 0) red[wid] = acc2;
    __syncthreads();
    if (tid == 0) {
      float tt = 0.f;
      #pragma unroll
      for (int w = 0; w < 8; ++w) tt += red[w];
      out[0] = tt * (1.0f / NB);
      g_ctr = 0;  // reset for next graph replay
    }
  }
}

extern "C" void kernel_launch(void* const* d_in, const int* in_sizes, int n_in,
                              void* d_out, int out_size) {
  const float* z1 = (const float*)d_in[0];
  const float* z2 = (const float*)d_in[1];
  (void)in_sizes; (void)n_in; (void)out_size;

  cudaFuncSetAttribute(hyp_fused, cudaFuncAttributeMaxDynamicSharedMemorySize, SMEM_TOTAL);

  dim3 grid(NBLK, NBLK);
  hyp_fused<<<grid, 256, SMEM_TOTAL>>>(z1, z2, (float*)d_out);
}